// round 4
// baseline (speedup 1.0000x reference)
#include <cuda_runtime.h>
#include <math.h>

#define Bb 4
#define Tt 128
#define Ss 512
#define Hh 512

// Scratch (device globals; allocation-free per harness rules)
__device__ float g_pq[Bb * Tt * Hh];     // query @ W_s
__device__ float g_pe[Bb * Ss * Hh];     // encoder @ W_h
__device__ float g_score[Bb * Tt * Ss];  // scores -> alignment (in place)
__device__ float g_ctx[Bb * Tt * Hh];    // alignment @ encoder

__device__ __forceinline__ float tanh_fast(float x) {
    float y;
    asm("tanh.approx.f32 %0, %1;" : "=f"(y) : "f"(x));
    return y;
}

__device__ __forceinline__ unsigned f2tf(float x) {
    unsigned r;
    asm("cvt.rna.tf32.f32 %0, %1;" : "=r"(r) : "f"(x));
    return r;
}

// m16n8k8 tf32 MMA, fp32 accumulate.
// A frag (row-major 16x8): a0=(g,t4) a1=(g+8,t4) a2=(g,t4+4) a3=(g+8,t4+4)
// B frag (col 8x8, kxn):   b0=(t4,g) b1=(t4+4,g)
// C frag: c0=(g,2t4) c1=(g,2t4+1) c2=(g+8,2t4) c3=(g+8,2t4+1)
__device__ __forceinline__ void mma_tf32(float4& c, const unsigned* a, const unsigned* b) {
    asm volatile(
        "mma.sync.aligned.m16n8k8.row.col.f32.tf32.tf32.f32 "
        "{%0,%1,%2,%3}, {%4,%5,%6,%7}, {%8,%9}, {%0,%1,%2,%3};"
        : "+f"(c.x), "+f"(c.y), "+f"(c.z), "+f"(c.w)
        : "r"(a[0]), "r"(a[1]), "r"(a[2]), "r"(a[3]), "r"(b[0]), "r"(b[1]));
}

// ---------------------------------------------------------------------------
// TF32 tensor-core GEMM: C[M,N] = concat_K(A0,A1) @ W, row-major, optional
// tanh epilogue, batched via blockIdx.z. Block tile 64x64xBK16, 128 threads
// (2x2 warps, each warp 32x32 via 2x4 m16n8k8 tiles). Inputs rounded to tf32
// at smem-staging time; accumulation fp32. Double-buffered smem + register
// prefetch. Requires: M%64==0, N%64==0, K%16==0, Ksplit%16==0.
// ---------------------------------------------------------------------------
template <bool DO_TANH>
__global__ __launch_bounds__(128) void gemm_tf32(
    const float* __restrict__ A0, const float* __restrict__ A1,
    const float* __restrict__ W, float* __restrict__ C,
    int N, int K, int Ksplit, int lda0, int lda1,
    long batchA0, long batchW, long batchC)
{
    constexpr int BM = 64, BN = 64, BK = 16;
    constexpr int LDA = BM + 4;   // stride 68: frag-LDS <=2-way conflicts
    constexpr int LDB = BN + 4;

    __shared__ unsigned As[2][BK][LDA];   // [k][m] tf32 bits
    __shared__ unsigned Wsm[2][BK][LDB];  // [k][n] tf32 bits

    const int b = blockIdx.z;
    const float* A0b = A0 + (long)b * batchA0;
    const float* Wb  = W  + (long)b * batchW;
    float*       Cb  = C  + (long)b * batchC;

    const int row0 = blockIdx.y * BM;
    const int col0 = blockIdx.x * BN;
    const int tid  = threadIdx.x;
    const int wid  = tid >> 5;
    const int lane = tid & 31;
    const int g    = lane >> 2;      // group id (0..7)
    const int t4   = lane & 3;       // thread-in-group (0..3)
    const int wm   = (wid >> 1) * 32;  // warp m offset in tile
    const int wn   = (wid & 1) * 32;   // warp n offset in tile

    float4 acc[2][4];
    #pragma unroll
    for (int i = 0; i < 2; i++)
        #pragma unroll
        for (int j = 0; j < 4; j++) acc[i][j] = make_float4(0.f, 0.f, 0.f, 0.f);

    float4 aF[2], wF[2];

    auto loadChunk = [&](int k0) {
        #pragma unroll
        for (int i = 0; i < 2; i++) {
            int idx = tid + i * 128;
            int r  = idx >> 2;            // 0..63 (m)
            int kc = (idx & 3) * 4;       // 0,4,8,12 (k)
            int gk = k0 + kc;
            const float* src = (gk < Ksplit)
                ? A0b + (long)(row0 + r) * lda0 + gk
                : A1  + (long)(row0 + r) * lda1 + (gk - Ksplit);
            aF[i] = *(const float4*)src;
        }
        #pragma unroll
        for (int i = 0; i < 2; i++) {
            int idx = tid + i * 128;
            int r = idx >> 4;             // 0..15 (k)
            int c = (idx & 15) * 4;       // n
            wF[i] = *(const float4*)(Wb + (long)(k0 + r) * N + col0 + c);
        }
    };
    auto storeChunk = [&](int buf) {
        #pragma unroll
        for (int i = 0; i < 2; i++) {
            int idx = tid + i * 128;
            int r  = idx >> 2;
            int kc = (idx & 3) * 4;
            As[buf][kc + 0][r] = f2tf(aF[i].x);
            As[buf][kc + 1][r] = f2tf(aF[i].y);
            As[buf][kc + 2][r] = f2tf(aF[i].z);
            As[buf][kc + 3][r] = f2tf(aF[i].w);
        }
        #pragma unroll
        for (int i = 0; i < 2; i++) {
            int idx = tid + i * 128;
            int r = idx >> 4;
            int c = (idx & 15) * 4;
            Wsm[buf][r][c + 0] = f2tf(wF[i].x);
            Wsm[buf][r][c + 1] = f2tf(wF[i].y);
            Wsm[buf][r][c + 2] = f2tf(wF[i].z);
            Wsm[buf][r][c + 3] = f2tf(wF[i].w);
        }
    };
    auto compute = [&](int buf) {
        #pragma unroll
        for (int kb = 0; kb < BK; kb += 8) {
            unsigned afr[2][4], bfr[4][2];
            #pragma unroll
            for (int mi = 0; mi < 2; mi++) {
                int m = wm + mi * 16 + g;
                afr[mi][0] = As[buf][kb + t4][m];
                afr[mi][1] = As[buf][kb + t4][m + 8];
                afr[mi][2] = As[buf][kb + t4 + 4][m];
                afr[mi][3] = As[buf][kb + t4 + 4][m + 8];
            }
            #pragma unroll
            for (int ni = 0; ni < 4; ni++) {
                int n = wn + ni * 8 + g;
                bfr[ni][0] = Wsm[buf][kb + t4][n];
                bfr[ni][1] = Wsm[buf][kb + t4 + 4][n];
            }
            #pragma unroll
            for (int mi = 0; mi < 2; mi++)
                #pragma unroll
                for (int ni = 0; ni < 4; ni++)
                    mma_tf32(acc[mi][ni], afr[mi], bfr[ni]);
        }
    };

    loadChunk(0);
    storeChunk(0);
    __syncthreads();

    int buf = 0;
    for (int k0 = BK; k0 < K; k0 += BK) {
        loadChunk(k0);            // next chunk's LDG in flight during compute
        compute(buf);
        storeChunk(buf ^ 1);
        __syncthreads();
        buf ^= 1;
    }
    compute(buf);

    // Epilogue: c0,c1 -> (row g, cols 2t4,2t4+1), c2,c3 -> row g+8
    #pragma unroll
    for (int mi = 0; mi < 2; mi++) {
        #pragma unroll
        for (int ni = 0; ni < 4; ni++) {
            float4 c = acc[mi][ni];
            if (DO_TANH) {
                c.x = tanhf(c.x); c.y = tanhf(c.y);
                c.z = tanhf(c.z); c.w = tanhf(c.w);
            }
            long r0 = row0 + wm + mi * 16 + g;
            long cc = col0 + wn + ni * 8 + t4 * 2;
            *(float2*)(Cb + r0 * N + cc)       = make_float2(c.x, c.y);
            *(float2*)(Cb + (r0 + 8) * N + cc) = make_float2(c.z, c.w);
        }
    }
}

// ---------------------------------------------------------------------------
// Score kernel: score[b,t,s] = sum_h v[h] * tanh(pq[b,t,h] + pe[b,s,h])
// Block tile: 16 t x 64 s, h chunked by 128 through smem. 256 threads,
// each owns a 2(t) x 2(s) register tile. MUFU.TANH bound by design.
// ---------------------------------------------------------------------------
__global__ __launch_bounds__(256) void score_kernel(const float* __restrict__ v)
{
    __shared__ float pe_s[64][132];
    __shared__ float pq_s[16][132];
    __shared__ float v_s[128];

    const int b  = blockIdx.z;
    const int t0 = blockIdx.y * 16;
    const int s0 = blockIdx.x * 64;
    const int tid = threadIdx.x;
    const int tx = tid & 31;   // s lane
    const int ty = tid >> 5;   // t pair (0..7)

    float acc00 = 0.f, acc01 = 0.f, acc10 = 0.f, acc11 = 0.f;

    for (int h0 = 0; h0 < Hh; h0 += 128) {
        for (int i = tid; i < 64 * 32; i += 256) {
            int r = i >> 5, c = (i & 31) * 4;
            float4 x = *(const float4*)(g_pe + (long)(b * Ss + s0 + r) * Hh + h0 + c);
            *(float4*)&pe_s[r][c] = x;
        }
        for (int i = tid; i < 16 * 32; i += 256) {
            int r = i >> 5, c = (i & 31) * 4;
            float4 x = *(const float4*)(g_pq + (long)(b * Tt + t0 + r) * Hh + h0 + c);
            *(float4*)&pq_s[r][c] = x;
        }
        if (tid < 32)
            *(float4*)&v_s[tid * 4] = *(const float4*)(v + h0 + tid * 4);
        __syncthreads();

        #pragma unroll 8
        for (int hh = 0; hh < 128; hh += 4) {
            float4 vv = *(const float4*)&v_s[hh];
            float4 a0 = *(const float4*)&pq_s[ty * 2 + 0][hh];
            float4 a1 = *(const float4*)&pq_s[ty * 2 + 1][hh];
            float4 e0 = *(const float4*)&pe_s[tx][hh];
            float4 e1 = *(const float4*)&pe_s[tx + 32][hh];

            acc00 += vv.x * tanh_fast(a0.x + e0.x) + vv.y * tanh_fast(a0.y + e0.y)
                   + vv.z * tanh_fast(a0.z + e0.z) + vv.w * tanh_fast(a0.w + e0.w);
            acc01 += vv.x * tanh_fast(a0.x + e1.x) + vv.y * tanh_fast(a0.y + e1.y)
                   + vv.z * tanh_fast(a0.z + e1.z) + vv.w * tanh_fast(a0.w + e1.w);
            acc10 += vv.x * tanh_fast(a1.x + e0.x) + vv.y * tanh_fast(a1.y + e0.y)
                   + vv.z * tanh_fast(a1.z + e0.z) + vv.w * tanh_fast(a1.w + e0.w);
            acc11 += vv.x * tanh_fast(a1.x + e1.x) + vv.y * tanh_fast(a1.y + e1.y)
                   + vv.z * tanh_fast(a1.z + e1.z) + vv.w * tanh_fast(a1.w + e1.w);
        }
        __syncthreads();
    }

    const int t_a = t0 + ty * 2, t_b = t_a + 1;
    g_score[(long)(b * Tt + t_a) * Ss + s0 + tx]      = acc00;
    g_score[(long)(b * Tt + t_a) * Ss + s0 + tx + 32] = acc01;
    g_score[(long)(b * Tt + t_b) * Ss + s0 + tx]      = acc10;
    g_score[(long)(b * Tt + t_b) * Ss + s0 + tx + 32] = acc11;
}

// ---------------------------------------------------------------------------
// Masked softmax over S, in place on g_score. One block (128 threads) per
// (b,t) row of 512 floats; each thread owns one float4.
// ---------------------------------------------------------------------------
__global__ __launch_bounds__(128) void softmax_kernel(const int* __restrict__ src_len)
{
    const int row = blockIdx.x;          // b*T + t
    const int b = row / Tt;
    const int len = src_len[b];
    const int tid = threadIdx.x;
    float* sp = g_score + (long)row * Ss;

    __shared__ float redm[4];
    __shared__ float reds[4];

    const int sbase = tid * 4;
    float4 x4 = *(const float4*)(sp + sbase);
    float xv[4] = {x4.x, x4.y, x4.z, x4.w};
    #pragma unroll
    for (int i = 0; i < 4; i++)
        if (sbase + i >= len) xv[i] = -3.0e38f;

    float m = fmaxf(fmaxf(xv[0], xv[1]), fmaxf(xv[2], xv[3]));
    #pragma unroll
    for (int off = 16; off; off >>= 1)
        m = fmaxf(m, __shfl_xor_sync(0xffffffffu, m, off));
    if ((tid & 31) == 0) redm[tid >> 5] = m;
    __syncthreads();
    m = fmaxf(fmaxf(redm[0], redm[1]), fmaxf(redm[2], redm[3]));

    float e[4];
    float ssum = 0.f;
    #pragma unroll
    for (int i = 0; i < 4; i++) {
        e[i] = (sbase + i < len) ? expf(xv[i] - m) : 0.f;
        ssum += e[i];
    }
    #pragma unroll
    for (int off = 16; off; off >>= 1)
        ssum += __shfl_xor_sync(0xffffffffu, ssum, off);
    if ((tid & 31) == 0) reds[tid >> 5] = ssum;
    __syncthreads();
    ssum = reds[0] + reds[1] + reds[2] + reds[3];

    const float inv = 1.0f / ssum;
    float4 o;
    o.x = e[0] * inv; o.y = e[1] * inv; o.z = e[2] * inv; o.w = e[3] * inv;
    *(float4*)(sp + sbase) = o;
}

// ---------------------------------------------------------------------------
// Launch
// ---------------------------------------------------------------------------
extern "C" void kernel_launch(void* const* d_in, const int* in_sizes, int n_in,
                              void* d_out, int out_size)
{
    const float* query = (const float*)d_in[0];  // (B,T,H)
    const float* enc   = (const float*)d_in[1];  // (B,S,H)
    const int*   slen  = (const int*)d_in[2];    // (B,)
    const float* W_h   = (const float*)d_in[3];  // (H,H)
    const float* W_s   = (const float*)d_in[4];  // (H,H)
    const float* v     = (const float*)d_in[5];  // (H,)
    const float* W_out = (const float*)d_in[6];  // (2H,H)
    float* out = (float*)d_out;                  // (B,T,H)

    float *pq, *pe, *score, *ctx;
    cudaGetSymbolAddress((void**)&pq,    g_pq);
    cudaGetSymbolAddress((void**)&pe,    g_pe);
    cudaGetSymbolAddress((void**)&score, g_score);
    cudaGetSymbolAddress((void**)&ctx,   g_ctx);

    // 1) pe = encoder @ W_h  (M=2048, N=512, K=512)
    gemm_tf32<false><<<dim3(8, 32, 1), 128>>>(enc, enc, W_h, pe,
        Hh, Hh, Hh, Hh, Hh, 0L, 0L, 0L);

    // 2) pq = query @ W_s    (M=512)
    gemm_tf32<false><<<dim3(8, 8, 1), 128>>>(query, query, W_s, pq,
        Hh, Hh, Hh, Hh, Hh, 0L, 0L, 0L);

    // 3) scores
    score_kernel<<<dim3(Ss / 64, Tt / 16, Bb), 256>>>(v);

    // 4) masked softmax (in place -> alignment)
    softmax_kernel<<<Bb * Tt, 128>>>(slen);

    // 5) context[b] = alignment[b] @ encoder[b]  (M=128, K=512)
    gemm_tf32<false><<<dim3(8, 2, Bb), 128>>>(score, score, enc, ctx,
        Hh, Ss, Ss, Ss, Ss, (long)Tt * Ss, (long)Ss * Hh, (long)Tt * Hh);

    // 6) out = tanh(concat(ctx, query) @ W_out)  (M=512, K=1024)
    gemm_tf32<true><<<dim3(8, 8, 1), 128>>>(ctx, query, W_out, out,
        Hh, 2 * Hh, Hh, Hh, Hh, 0L, 0L, 0L);
}

// round 6
// speedup vs baseline: 1.8399x; 1.8399x over previous
#include <cuda_runtime.h>
#include <math.h>
#include <stdint.h>

#define Bb 4
#define Tt 128
#define Ss 512
#define Hh 512

// Scratch (device globals; allocation-free per harness rules)
__device__ float g_pq[Bb * Tt * Hh];     // query @ W_s
__device__ float g_pe[Bb * Ss * Hh];     // encoder @ W_h
__device__ float g_qWo[Bb * Tt * Hh];    // query @ W_out[H:2H]  (precomputed)
__device__ float g_score[Bb * Tt * Ss];  // scores -> alignment (in place)
__device__ float g_ctx[Bb * Tt * Hh];    // alignment @ encoder

// ---------------------------------------------------------------------------
// f16x2 helpers
// ---------------------------------------------------------------------------
__device__ __forceinline__ unsigned pack_h2(float lo, float hi) {
    unsigned r;
    asm("cvt.rn.f16x2.f32 %0, %1, %2;" : "=r"(r) : "f"(hi), "f"(lo));
    return r;
}

// x = a + e (f16x2); t = tanh(x); ch += t * v  (all packed f16x2)
#define STEP_H2(aP, eP, vP, ch) do {                                   \
    unsigned _x, _t;                                                   \
    asm("add.rn.f16x2 %0, %1, %2;" : "=r"(_x) : "r"(aP), "r"(eP));     \
    asm("tanh.approx.f16x2 %0, %1;" : "=r"(_t) : "r"(_x));             \
    asm("fma.rn.f16x2 %0, %1, %2, %3;"                                 \
        : "=r"(ch) : "r"(_t), "r"(vP), "r"(ch));                       \
} while (0)

// unpack packed chunk-accumulator into fp32 accumulator
#define FLUSH_H2(ch, acc) do {                                         \
    float _l, _h;                                                      \
    asm("{.reg .b16 l, h; mov.b32 {l, h}, %2;"                         \
        " cvt.f32.f16 %0, l; cvt.f32.f16 %1, h;}"                      \
        : "=f"(_l), "=f"(_h) : "r"(ch));                               \
    acc += _l; acc += _h;                                              \
} while (0)

// ---------------------------------------------------------------------------
// SGEMM core (round-2 proven config): 32x64 block tile, BK=32, 128 threads,
// 4x4 micro-tile, double-buffered smem + register prefetch.
// C[row0:+32, col0:+64] = A[rows, K] @ W[K, N] (+ INIT) (tanh?).
// ---------------------------------------------------------------------------
template <bool DO_TANH, bool HAS_INIT>
__device__ __forceinline__ void gemm_core(
    const float* __restrict__ A, const float* __restrict__ W,
    const float* __restrict__ INIT, float* __restrict__ C,
    int row0, int col0, int N, int K, int lda,
    float (&As)[2][32][33], float (&Ws)[2][32][64])
{
    const int tid = threadIdx.x;
    const int txn = tid & 15;
    const int tym = tid >> 4;

    float4 aF[2], wF[4];
    float acc[4][4] = {};

    auto loadChunk = [&](int k0) {
        #pragma unroll
        for (int i = 0; i < 2; i++) {
            int idx = tid + i * 128;
            int r  = idx >> 3;
            int kc = (idx & 7) * 4;
            aF[i] = *(const float4*)(A + (long)(row0 + r) * lda + k0 + kc);
        }
        #pragma unroll
        for (int i = 0; i < 4; i++) {
            int idx = tid + i * 128;
            int r = idx >> 4;
            int c = (idx & 15) * 4;
            wF[i] = *(const float4*)(W + (long)(k0 + r) * N + col0 + c);
        }
    };
    auto storeChunk = [&](int buf) {
        #pragma unroll
        for (int i = 0; i < 2; i++) {
            int idx = tid + i * 128;
            int r  = idx >> 3;
            int kc = (idx & 7) * 4;
            As[buf][r][kc + 0] = aF[i].x;
            As[buf][r][kc + 1] = aF[i].y;
            As[buf][r][kc + 2] = aF[i].z;
            As[buf][r][kc + 3] = aF[i].w;
        }
        #pragma unroll
        for (int i = 0; i < 4; i++) {
            int idx = tid + i * 128;
            int r = idx >> 4;
            int c = (idx & 15) * 4;
            *(float4*)&Ws[buf][r][c] = wF[i];
        }
    };
    auto compute = [&](int buf) {
        #pragma unroll
        for (int kk = 0; kk < 32; kk++) {
            float a[4];
            #pragma unroll
            for (int i = 0; i < 4; i++) a[i] = As[buf][tym * 4 + i][kk];
            float4 w = *(const float4*)&Ws[buf][kk][txn * 4];
            float wr[4] = {w.x, w.y, w.z, w.w};
            #pragma unroll
            for (int i = 0; i < 4; i++)
                #pragma unroll
                for (int j = 0; j < 4; j++)
                    acc[i][j] += a[i] * wr[j];
        }
    };

    loadChunk(0);
    storeChunk(0);
    __syncthreads();

    int buf = 0;
    for (int k0 = 32; k0 < K; k0 += 32) {
        loadChunk(k0);
        compute(buf);
        storeChunk(buf ^ 1);
        __syncthreads();
        buf ^= 1;
    }
    compute(buf);

    #pragma unroll
    for (int i = 0; i < 4; i++) {
        int r = row0 + tym * 4 + i;
        float4 o;
        o.x = acc[i][0]; o.y = acc[i][1]; o.z = acc[i][2]; o.w = acc[i][3];
        if (HAS_INIT) {
            float4 b = *(const float4*)(INIT + (long)r * N + col0 + txn * 4);
            o.x += b.x; o.y += b.y; o.z += b.z; o.w += b.w;
        }
        if (DO_TANH) {
            o.x = tanhf(o.x); o.y = tanhf(o.y);
            o.z = tanhf(o.z); o.w = tanhf(o.w);
        }
        *(float4*)(C + (long)r * N + col0 + txn * 4) = o;
    }
}

// ---------------------------------------------------------------------------
// Phase 1 mega-GEMM: pe = enc@W_h (yb 0..63), pq = q@W_s (64..79),
// qWo = q@W_out[H:2H] (80..95). All M%32, N=512, K=512.
// ---------------------------------------------------------------------------
__global__ __launch_bounds__(128) void phase1_kernel(
    const float* __restrict__ enc, const float* __restrict__ query,
    const float* __restrict__ W_h, const float* __restrict__ W_s,
    const float* __restrict__ W_out)
{
    __shared__ float As[2][32][33];
    __shared__ float Ws[2][32][64];
    const int yb = blockIdx.y;
    const int col0 = blockIdx.x * 64;
    if (yb < 64) {
        gemm_core<false, false>(enc, W_h, nullptr, g_pe,
                                yb * 32, col0, Hh, Hh, Hh, As, Ws);
    } else if (yb < 80) {
        gemm_core<false, false>(query, W_s, nullptr, g_pq,
                                (yb - 64) * 32, col0, Hh, Hh, Hh, As, Ws);
    } else {
        gemm_core<false, false>(query, W_out + (long)Hh * Hh, nullptr, g_qWo,
                                (yb - 80) * 32, col0, Hh, Hh, Hh, As, Ws);
    }
}

// ctx[b] = alignment[b] @ enc[b]  (M=128 per batch)
__global__ __launch_bounds__(128) void ctx_kernel(const float* __restrict__ enc)
{
    __shared__ float As[2][32][33];
    __shared__ float Ws[2][32][64];
    const int b = blockIdx.z;
    gemm_core<false, false>(g_score + (long)b * Tt * Ss,
                            enc + (long)b * Ss * Hh, nullptr,
                            g_ctx + (long)b * Tt * Hh,
                            blockIdx.y * 32, blockIdx.x * 64, Hh, Ss, Ss, As, Ws);
}

// out = tanh(ctx @ W_out[0:H] + qWo)
__global__ __launch_bounds__(128) void out_kernel(const float* __restrict__ W_out,
                                                  float* __restrict__ out)
{
    __shared__ float As[2][32][33];
    __shared__ float Ws[2][32][64];
    gemm_core<true, true>(g_ctx, W_out, g_qWo, out,
                          blockIdx.y * 32, blockIdx.x * 64, Hh, Hh, Hh, As, Ws);
}

// ---------------------------------------------------------------------------
// Score kernel v2 (packed f16x2 tanh):
// score[b,t,s] = sum_h v[h] * tanh(pq[b,t,h] + pe[b,s,h])
// Tiles staged in smem as packed f16x2 pairs (pitch 68 words, 16B-aligned
// uint4 reads). Each thread owns a 2(t) x 2(s) register tile. Products
// v*tanh accumulated in f16x2 via HFMA2 over 4-pair chunks (8 h), flushed
// to fp32 per chunk -> only 2 cvt.f32.f16 per 32 tanh. MUFU halved vs f32.
// ---------------------------------------------------------------------------
__global__ __launch_bounds__(256) void score2_kernel(const float* __restrict__ v)
{
    __shared__ unsigned pe_p[64][68];   // [s][h-pair]
    __shared__ unsigned pq_p[16][68];   // [t][h-pair]
    __shared__ unsigned v_p[64];

    const int b  = blockIdx.z;
    const int t0 = blockIdx.y * 16;
    const int s0 = blockIdx.x * 64;
    const int tid = threadIdx.x;
    const int tx = tid & 31;   // s lane
    const int ty = tid >> 5;   // t pair (0..7)

    float acc00 = 0.f, acc01 = 0.f, acc10 = 0.f, acc11 = 0.f;

    for (int h0 = 0; h0 < Hh; h0 += 128) {
        // stage pe: 64 rows x 128 h -> 64 pairs/row
        for (int i = tid; i < 64 * 32; i += 256) {
            int r = i >> 5, q = i & 31;
            float4 x = *(const float4*)(g_pe + (long)(b * Ss + s0 + r) * Hh + h0 + q * 4);
            *(uint2*)&pe_p[r][q * 2] = make_uint2(pack_h2(x.x, x.y), pack_h2(x.z, x.w));
        }
        // stage pq: 16 rows x 128 h
        for (int i = tid; i < 16 * 32; i += 256) {
            int r = i >> 5, q = i & 31;
            float4 x = *(const float4*)(g_pq + (long)(b * Tt + t0 + r) * Hh + h0 + q * 4);
            *(uint2*)&pq_p[r][q * 2] = make_uint2(pack_h2(x.x, x.y), pack_h2(x.z, x.w));
        }
        if (tid < 32) {
            float4 x = *(const float4*)(v + h0 + tid * 4);
            *(uint2*)&v_p[tid * 2] = make_uint2(pack_h2(x.x, x.y), pack_h2(x.z, x.w));
        }
        __syncthreads();

        #pragma unroll 4
        for (int hp = 0; hp < 64; hp += 4) {   // 4 pairs = 8 h = one chunk
            uint4 a0 = *(const uint4*)&pq_p[ty * 2 + 0][hp];
            uint4 a1 = *(const uint4*)&pq_p[ty * 2 + 1][hp];
            uint4 e0 = *(const uint4*)&pe_p[tx][hp];
            uint4 e1 = *(const uint4*)&pe_p[tx + 32][hp];
            uint4 vv = *(const uint4*)&v_p[hp];

            unsigned ch00 = 0u, ch01 = 0u, ch10 = 0u, ch11 = 0u;
            STEP_H2(a0.x, e0.x, vv.x, ch00); STEP_H2(a0.y, e0.y, vv.y, ch00);
            STEP_H2(a0.z, e0.z, vv.z, ch00); STEP_H2(a0.w, e0.w, vv.w, ch00);
            STEP_H2(a0.x, e1.x, vv.x, ch01); STEP_H2(a0.y, e1.y, vv.y, ch01);
            STEP_H2(a0.z, e1.z, vv.z, ch01); STEP_H2(a0.w, e1.w, vv.w, ch01);
            STEP_H2(a1.x, e0.x, vv.x, ch10); STEP_H2(a1.y, e0.y, vv.y, ch10);
            STEP_H2(a1.z, e0.z, vv.z, ch10); STEP_H2(a1.w, e0.w, vv.w, ch10);
            STEP_H2(a1.x, e1.x, vv.x, ch11); STEP_H2(a1.y, e1.y, vv.y, ch11);
            STEP_H2(a1.z, e1.z, vv.z, ch11); STEP_H2(a1.w, e1.w, vv.w, ch11);
            FLUSH_H2(ch00, acc00); FLUSH_H2(ch01, acc01);
            FLUSH_H2(ch10, acc10); FLUSH_H2(ch11, acc11);
        }
        __syncthreads();
    }

    const int t_a = t0 + ty * 2, t_b = t_a + 1;
    g_score[(long)(b * Tt + t_a) * Ss + s0 + tx]      = acc00;
    g_score[(long)(b * Tt + t_a) * Ss + s0 + tx + 32] = acc01;
    g_score[(long)(b * Tt + t_b) * Ss + s0 + tx]      = acc10;
    g_score[(long)(b * Tt + t_b) * Ss + s0 + tx + 32] = acc11;
}

// ---------------------------------------------------------------------------
// Masked softmax over S, in place on g_score. One block (128 threads) per
// (b,t) row of 512 floats; each thread owns one float4.
// ---------------------------------------------------------------------------
__global__ __launch_bounds__(128) void softmax_kernel(const int* __restrict__ src_len)
{
    const int row = blockIdx.x;          // b*T + t
    const int b = row / Tt;
    const int len = src_len[b];
    const int tid = threadIdx.x;
    float* sp = g_score + (long)row * Ss;

    __shared__ float redm[4];
    __shared__ float reds[4];

    const int sbase = tid * 4;
    float4 x4 = *(const float4*)(sp + sbase);
    float xv[4] = {x4.x, x4.y, x4.z, x4.w};
    #pragma unroll
    for (int i = 0; i < 4; i++)
        if (sbase + i >= len) xv[i] = -3.0e38f;

    float m = fmaxf(fmaxf(xv[0], xv[1]), fmaxf(xv[2], xv[3]));
    #pragma unroll
    for (int off = 16; off; off >>= 1)
        m = fmaxf(m, __shfl_xor_sync(0xffffffffu, m, off));
    if ((tid & 31) == 0) redm[tid >> 5] = m;
    __syncthreads();
    m = fmaxf(fmaxf(redm[0], redm[1]), fmaxf(redm[2], redm[3]));

    float e[4];
    float ssum = 0.f;
    #pragma unroll
    for (int i = 0; i < 4; i++) {
        e[i] = (sbase + i < len) ? expf(xv[i] - m) : 0.f;
        ssum += e[i];
    }
    #pragma unroll
    for (int off = 16; off; off >>= 1)
        ssum += __shfl_xor_sync(0xffffffffu, ssum, off);
    if ((tid & 31) == 0) reds[tid >> 5] = ssum;
    __syncthreads();
    ssum = reds[0] + reds[1] + reds[2] + reds[3];

    const float inv = 1.0f / ssum;
    float4 o;
    o.x = e[0] * inv; o.y = e[1] * inv; o.z = e[2] * inv; o.w = e[3] * inv;
    *(float4*)(sp + sbase) = o;
}

// ---------------------------------------------------------------------------
// Launch
// ---------------------------------------------------------------------------
extern "C" void kernel_launch(void* const* d_in, const int* in_sizes, int n_in,
                              void* d_out, int out_size)
{
    const float* query = (const float*)d_in[0];  // (B,T,H)
    const float* enc   = (const float*)d_in[1];  // (B,S,H)
    const int*   slen  = (const int*)d_in[2];    // (B,)
    const float* W_h   = (const float*)d_in[3];  // (H,H)
    const float* W_s   = (const float*)d_in[4];  // (H,H)
    const float* v     = (const float*)d_in[5];  // (H,)
    const float* W_out = (const float*)d_in[6];  // (2H,H)
    float* out = (float*)d_out;                  // (B,T,H)

    // 1) pe, pq, qWo in one launch (768 blocks)
    phase1_kernel<<<dim3(8, 96, 1), 128>>>(enc, query, W_h, W_s, W_out);

    // 2) scores (f16x2 tanh)
    score2_kernel<<<dim3(Ss / 64, Tt / 16, Bb), 256>>>(v);

    // 3) masked softmax (in place -> alignment)
    softmax_kernel<<<Bb * Tt, 128>>>(slen);

    // 4) context = alignment @ encoder (batched)
    ctx_kernel<<<dim3(8, 4, Bb), 128>>>(enc);

    // 5) out = tanh(ctx @ W_out[0:H] + qWo)
    out_kernel<<<dim3(8, 16, 1), 128>>>(W_out, out);
}

// round 7
// speedup vs baseline: 2.1234x; 1.1541x over previous
#include <cuda_runtime.h>
#include <math.h>
#include <stdint.h>

#define Bb 4
#define Tt 128
#define Ss 512
#define Hh 512
#define BTH (Bb * Tt * Hh)

// Scratch (device globals; allocation-free per harness rules)
__device__ float g_pq[BTH];              // query @ W_s
__device__ float g_pe[Bb * Ss * Hh];     // encoder @ W_h
__device__ float g_qWo[BTH];             // query @ W_out[H:2H]
__device__ float g_score[Bb * Tt * Ss];  // scores -> alignment (in place)
__device__ float g_ctx[BTH];             // alignment @ encoder
__device__ float g_cp[4 * BTH];          // ctx split-K partials
__device__ float g_op[4 * BTH];          // out split-K partials

// ---------------------------------------------------------------------------
// f16x2 helpers
// ---------------------------------------------------------------------------
__device__ __forceinline__ unsigned pack_h2(float lo, float hi) {
    unsigned r;
    asm("cvt.rn.f16x2.f32 %0, %1, %2;" : "=r"(r) : "f"(hi), "f"(lo));
    return r;
}

#define STEP_H2(aP, eP, vP, ch) do {                                   \
    unsigned _x, _t;                                                   \
    asm("add.rn.f16x2 %0, %1, %2;" : "=r"(_x) : "r"(aP), "r"(eP));     \
    asm("tanh.approx.f16x2 %0, %1;" : "=r"(_t) : "r"(_x));             \
    asm("fma.rn.f16x2 %0, %1, %2, %3;"                                 \
        : "=r"(ch) : "r"(_t), "r"(vP), "r"(ch));                       \
} while (0)

#define FLUSH_H2(ch, acc) do {                                         \
    float _l, _h;                                                      \
    asm("{.reg .b16 l, h; mov.b32 {l, h}, %2;"                         \
        " cvt.f32.f16 %0, l; cvt.f32.f16 %1, h;}"                      \
        : "=f"(_l), "=f"(_h) : "r"(ch));                               \
    acc += _l; acc += _h;                                              \
} while (0)

// ---------------------------------------------------------------------------
// SGEMM core: 32x64 block tile, BK=32, 128 threads, 4x4 micro-tile,
// double-buffered smem + register prefetch.
// ---------------------------------------------------------------------------
__device__ __forceinline__ void gemm_core(
    const float* __restrict__ A, const float* __restrict__ W,
    float* __restrict__ C,
    int row0, int col0, int N, int K, int lda,
    float (&As)[2][32][33], float (&Ws)[2][32][64])
{
    const int tid = threadIdx.x;
    const int txn = tid & 15;
    const int tym = tid >> 4;

    float4 aF[2], wF[4];
    float acc[4][4] = {};

    auto loadChunk = [&](int k0) {
        #pragma unroll
        for (int i = 0; i < 2; i++) {
            int idx = tid + i * 128;
            int r  = idx >> 3;
            int kc = (idx & 7) * 4;
            aF[i] = *(const float4*)(A + (long)(row0 + r) * lda + k0 + kc);
        }
        #pragma unroll
        for (int i = 0; i < 4; i++) {
            int idx = tid + i * 128;
            int r = idx >> 4;
            int c = (idx & 15) * 4;
            wF[i] = *(const float4*)(W + (long)(k0 + r) * N + col0 + c);
        }
    };
    auto storeChunk = [&](int buf) {
        #pragma unroll
        for (int i = 0; i < 2; i++) {
            int idx = tid + i * 128;
            int r  = idx >> 3;
            int kc = (idx & 7) * 4;
            As[buf][r][kc + 0] = aF[i].x;
            As[buf][r][kc + 1] = aF[i].y;
            As[buf][r][kc + 2] = aF[i].z;
            As[buf][r][kc + 3] = aF[i].w;
        }
        #pragma unroll
        for (int i = 0; i < 4; i++) {
            int idx = tid + i * 128;
            int r = idx >> 4;
            int c = (idx & 15) * 4;
            *(float4*)&Ws[buf][r][c] = wF[i];
        }
    };
    auto compute = [&](int buf) {
        #pragma unroll
        for (int kk = 0; kk < 32; kk++) {
            float a[4];
            #pragma unroll
            for (int i = 0; i < 4; i++) a[i] = As[buf][tym * 4 + i][kk];
            float4 w = *(const float4*)&Ws[buf][kk][txn * 4];
            float wr[4] = {w.x, w.y, w.z, w.w};
            #pragma unroll
            for (int i = 0; i < 4; i++)
                #pragma unroll
                for (int j = 0; j < 4; j++)
                    acc[i][j] += a[i] * wr[j];
        }
    };

    loadChunk(0);
    storeChunk(0);
    __syncthreads();

    int buf = 0;
    for (int k0 = 32; k0 < K; k0 += 32) {
        loadChunk(k0);
        compute(buf);
        storeChunk(buf ^ 1);
        __syncthreads();
        buf ^= 1;
    }
    compute(buf);

    #pragma unroll
    for (int i = 0; i < 4; i++) {
        int r = row0 + tym * 4 + i;
        float4 o;
        o.x = acc[i][0]; o.y = acc[i][1]; o.z = acc[i][2]; o.w = acc[i][3];
        *(float4*)(C + (long)r * N + col0 + txn * 4) = o;
    }
}

// ---------------------------------------------------------------------------
// Phase 1 mega-GEMM: pe = enc@W_h (yb 0..63), pq = q@W_s (64..79),
// qWo = q@W_out[H:2H] (80..95). All N=512, K=512.
// ---------------------------------------------------------------------------
__global__ __launch_bounds__(128) void phase1_kernel(
    const float* __restrict__ enc, const float* __restrict__ query,
    const float* __restrict__ W_h, const float* __restrict__ W_s,
    const float* __restrict__ W_out)
{
    __shared__ float As[2][32][33];
    __shared__ float Ws[2][32][64];
    const int yb = blockIdx.y;
    const int col0 = blockIdx.x * 64;
    if (yb < 64) {
        gemm_core(enc, W_h, g_pe, yb * 32, col0, Hh, Hh, Hh, As, Ws);
    } else if (yb < 80) {
        gemm_core(query, W_s, g_pq, (yb - 64) * 32, col0, Hh, Hh, Hh, As, Ws);
    } else {
        gemm_core(query, W_out + (long)Hh * Hh, g_qWo,
                  (yb - 80) * 32, col0, Hh, Hh, Hh, As, Ws);
    }
}

// ---------------------------------------------------------------------------
// ctx split-K: partial[seg] = align[b][:, seg*128:(seg+1)*128] @ enc[b][seg...]
// grid (8, 4, 16): x = n-tile, y = m-tile (within batch), z = b*4+seg.
// ---------------------------------------------------------------------------
__global__ __launch_bounds__(128) void ctx_kernel(const float* __restrict__ enc)
{
    __shared__ float As[2][32][33];
    __shared__ float Ws[2][32][64];
    const int b   = blockIdx.z & 3;
    const int seg = blockIdx.z >> 2;
    gemm_core(g_score + (long)b * Tt * Ss + seg * 128,
              enc + (long)b * Ss * Hh + (long)seg * 128 * Hh,
              g_cp + (long)seg * BTH + (long)b * Tt * Hh,
              blockIdx.y * 32, blockIdx.x * 64, Hh, 128, Ss, As, Ws);
}

__global__ __launch_bounds__(256) void ctx_reduce_kernel()
{
    int i = blockIdx.x * 256 + threadIdx.x;   // float4 index
    float4 a = ((const float4*)g_cp)[i];
    float4 b = ((const float4*)(g_cp + BTH))[i];
    float4 c = ((const float4*)(g_cp + 2 * BTH))[i];
    float4 d = ((const float4*)(g_cp + 3 * BTH))[i];
    float4 o;
    o.x = (a.x + b.x) + (c.x + d.x);
    o.y = (a.y + b.y) + (c.y + d.y);
    o.z = (a.z + b.z) + (c.z + d.z);
    o.w = (a.w + b.w) + (c.w + d.w);
    ((float4*)g_ctx)[i] = o;
}

// ---------------------------------------------------------------------------
// out split-K: partial[seg] = ctx[:, seg*128:...] @ W_out[seg*128:..., :]
// grid (8, 16, 4): z = seg. Final reduce adds qWo and applies tanh.
// ---------------------------------------------------------------------------
__global__ __launch_bounds__(128) void out_kernel(const float* __restrict__ W_out)
{
    __shared__ float As[2][32][33];
    __shared__ float Ws[2][32][64];
    const int seg = blockIdx.z;
    gemm_core(g_ctx + seg * 128,
              W_out + (long)seg * 128 * Hh,
              g_op + (long)seg * BTH,
              blockIdx.y * 32, blockIdx.x * 64, Hh, 128, Hh, As, Ws);
}

__global__ __launch_bounds__(256) void out_reduce_kernel(float* __restrict__ out)
{
    int i = blockIdx.x * 256 + threadIdx.x;   // float4 index
    float4 a = ((const float4*)g_op)[i];
    float4 b = ((const float4*)(g_op + BTH))[i];
    float4 c = ((const float4*)(g_op + 2 * BTH))[i];
    float4 d = ((const float4*)(g_op + 3 * BTH))[i];
    float4 q = ((const float4*)g_qWo)[i];
    float4 o;
    o.x = tanhf((a.x + b.x) + (c.x + d.x) + q.x);
    o.y = tanhf((a.y + b.y) + (c.y + d.y) + q.y);
    o.z = tanhf((a.z + b.z) + (c.z + d.z) + q.z);
    o.w = tanhf((a.w + b.w) + (c.w + d.w) + q.w);
    ((float4*)out)[i] = o;
}

// ---------------------------------------------------------------------------
// Score kernel (packed f16x2 tanh):
// score[b,t,s] = sum_h v[h] * tanh(pq[b,t,h] + pe[b,s,h])
// ---------------------------------------------------------------------------
__global__ __launch_bounds__(256) void score2_kernel(const float* __restrict__ v)
{
    __shared__ unsigned pe_p[64][68];   // [s][h-pair]
    __shared__ unsigned pq_p[16][68];   // [t][h-pair]
    __shared__ unsigned v_p[64];

    const int b  = blockIdx.z;
    const int t0 = blockIdx.y * 16;
    const int s0 = blockIdx.x * 64;
    const int tid = threadIdx.x;
    const int tx = tid & 31;   // s lane
    const int ty = tid >> 5;   // t pair (0..7)

    float acc00 = 0.f, acc01 = 0.f, acc10 = 0.f, acc11 = 0.f;

    for (int h0 = 0; h0 < Hh; h0 += 128) {
        for (int i = tid; i < 64 * 32; i += 256) {
            int r = i >> 5, q = i & 31;
            float4 x = *(const float4*)(g_pe + (long)(b * Ss + s0 + r) * Hh + h0 + q * 4);
            *(uint2*)&pe_p[r][q * 2] = make_uint2(pack_h2(x.x, x.y), pack_h2(x.z, x.w));
        }
        for (int i = tid; i < 16 * 32; i += 256) {
            int r = i >> 5, q = i & 31;
            float4 x = *(const float4*)(g_pq + (long)(b * Tt + t0 + r) * Hh + h0 + q * 4);
            *(uint2*)&pq_p[r][q * 2] = make_uint2(pack_h2(x.x, x.y), pack_h2(x.z, x.w));
        }
        if (tid < 32) {
            float4 x = *(const float4*)(v + h0 + tid * 4);
            *(uint2*)&v_p[tid * 2] = make_uint2(pack_h2(x.x, x.y), pack_h2(x.z, x.w));
        }
        __syncthreads();

        #pragma unroll 4
        for (int hp = 0; hp < 64; hp += 4) {   // 4 pairs = 8 h per chunk
            uint4 a0 = *(const uint4*)&pq_p[ty * 2 + 0][hp];
            uint4 a1 = *(const uint4*)&pq_p[ty * 2 + 1][hp];
            uint4 e0 = *(const uint4*)&pe_p[tx][hp];
            uint4 e1 = *(const uint4*)&pe_p[tx + 32][hp];
            uint4 vv = *(const uint4*)&v_p[hp];

            unsigned ch00 = 0u, ch01 = 0u, ch10 = 0u, ch11 = 0u;
            STEP_H2(a0.x, e0.x, vv.x, ch00); STEP_H2(a0.y, e0.y, vv.y, ch00);
            STEP_H2(a0.z, e0.z, vv.z, ch00); STEP_H2(a0.w, e0.w, vv.w, ch00);
            STEP_H2(a0.x, e1.x, vv.x, ch01); STEP_H2(a0.y, e1.y, vv.y, ch01);
            STEP_H2(a0.z, e1.z, vv.z, ch01); STEP_H2(a0.w, e1.w, vv.w, ch01);
            STEP_H2(a1.x, e0.x, vv.x, ch10); STEP_H2(a1.y, e0.y, vv.y, ch10);
            STEP_H2(a1.z, e0.z, vv.z, ch10); STEP_H2(a1.w, e0.w, vv.w, ch10);
            STEP_H2(a1.x, e1.x, vv.x, ch11); STEP_H2(a1.y, e1.y, vv.y, ch11);
            STEP_H2(a1.z, e1.z, vv.z, ch11); STEP_H2(a1.w, e1.w, vv.w, ch11);
            FLUSH_H2(ch00, acc00); FLUSH_H2(ch01, acc01);
            FLUSH_H2(ch10, acc10); FLUSH_H2(ch11, acc11);
        }
        __syncthreads();
    }

    const int t_a = t0 + ty * 2, t_b = t_a + 1;
    g_score[(long)(b * Tt + t_a) * Ss + s0 + tx]      = acc00;
    g_score[(long)(b * Tt + t_a) * Ss + s0 + tx + 32] = acc01;
    g_score[(long)(b * Tt + t_b) * Ss + s0 + tx]      = acc10;
    g_score[(long)(b * Tt + t_b) * Ss + s0 + tx + 32] = acc11;
}

// ---------------------------------------------------------------------------
// Masked softmax over S, in place on g_score.
// ---------------------------------------------------------------------------
__global__ __launch_bounds__(128) void softmax_kernel(const int* __restrict__ src_len)
{
    const int row = blockIdx.x;
    const int b = row / Tt;
    const int len = src_len[b];
    const int tid = threadIdx.x;
    float* sp = g_score + (long)row * Ss;

    __shared__ float redm[4];
    __shared__ float reds[4];

    const int sbase = tid * 4;
    float4 x4 = *(const float4*)(sp + sbase);
    float xv[4] = {x4.x, x4.y, x4.z, x4.w};
    #pragma unroll
    for (int i = 0; i < 4; i++)
        if (sbase + i >= len) xv[i] = -3.0e38f;

    float m = fmaxf(fmaxf(xv[0], xv[1]), fmaxf(xv[2], xv[3]));
    #pragma unroll
    for (int off = 16; off; off >>= 1)
        m = fmaxf(m, __shfl_xor_sync(0xffffffffu, m, off));
    if ((tid & 31) == 0) redm[tid >> 5] = m;
    __syncthreads();
    m = fmaxf(fmaxf(redm[0], redm[1]), fmaxf(redm[2], redm[3]));

    float e[4];
    float ssum = 0.f;
    #pragma unroll
    for (int i = 0; i < 4; i++) {
        e[i] = (sbase + i < len) ? expf(xv[i] - m) : 0.f;
        ssum += e[i];
    }
    #pragma unroll
    for (int off = 16; off; off >>= 1)
        ssum += __shfl_xor_sync(0xffffffffu, ssum, off);
    if ((tid & 31) == 0) reds[tid >> 5] = ssum;
    __syncthreads();
    ssum = reds[0] + reds[1] + reds[2] + reds[3];

    const float inv = 1.0f / ssum;
    float4 o;
    o.x = e[0] * inv; o.y = e[1] * inv; o.z = e[2] * inv; o.w = e[3] * inv;
    *(float4*)(sp + sbase) = o;
}

// ---------------------------------------------------------------------------
// Launch
// ---------------------------------------------------------------------------
extern "C" void kernel_launch(void* const* d_in, const int* in_sizes, int n_in,
                              void* d_out, int out_size)
{
    const float* query = (const float*)d_in[0];  // (B,T,H)
    const float* enc   = (const float*)d_in[1];  // (B,S,H)
    const int*   slen  = (const int*)d_in[2];    // (B,)
    const float* W_h   = (const float*)d_in[3];  // (H,H)
    const float* W_s   = (const float*)d_in[4];  // (H,H)
    const float* v     = (const float*)d_in[5];  // (H,)
    const float* W_out = (const float*)d_in[6];  // (2H,H)
    float* out = (float*)d_out;                  // (B,T,H)

    // 1) pe, pq, qWo in one launch (768 blocks)
    phase1_kernel<<<dim3(8, 96, 1), 128>>>(enc, query, W_h, W_s, W_out);

    // 2) scores (f16x2 tanh)
    score2_kernel<<<dim3(Ss / 64, Tt / 16, Bb), 256>>>(v);

    // 3) masked softmax (in place -> alignment)
    softmax_kernel<<<Bb * Tt, 128>>>(slen);

    // 4) context = alignment @ encoder : split-K 4 (512 blocks) + reduce
    ctx_kernel<<<dim3(8, 4, 16), 128>>>(enc);
    ctx_reduce_kernel<<<BTH / 4 / 256, 256>>>();

    // 5) out = tanh(ctx @ W_out[0:H] + qWo) : split-K 4 (512 blocks) + reduce
    out_kernel<<<dim3(8, 16, 4), 128>>>(W_out);
    out_reduce_kernel<<<BTH / 4 / 256, 256>>>(out);
}

// round 8
// speedup vs baseline: 2.1336x; 1.0048x over previous
#include <cuda_runtime.h>
#include <math.h>
#include <stdint.h>

#define Bb 4
#define Tt 128
#define Ss 512
#define Hh 512
#define BTH (Bb * Tt * Hh)

// Scratch (device globals; allocation-free per harness rules)
__device__ float g_pq[BTH];              // query @ W_s
__device__ float g_pe[Bb * Ss * Hh];     // encoder @ W_h
__device__ float g_qWo[BTH];             // query @ W_out[H:2H]
__device__ float g_score[Bb * Tt * Ss];  // scores -> alignment (in place)
__device__ float g_ctx[BTH];             // alignment @ encoder
__device__ float g_cp[4 * BTH];          // ctx split-K partials
__device__ float g_op[4 * BTH];          // out split-K partials

// ---------------------------------------------------------------------------
// f16x2 helpers
// ---------------------------------------------------------------------------
__device__ __forceinline__ unsigned pack_h2(float lo, float hi) {
    unsigned r;
    asm("cvt.rn.f16x2.f32 %0, %1, %2;" : "=r"(r) : "f"(hi), "f"(lo));
    return r;
}

#define STEP_H2(aP, eP, vP, ch) do {                                   \
    unsigned _x, _t;                                                   \
    asm("add.rn.f16x2 %0, %1, %2;" : "=r"(_x) : "r"(aP), "r"(eP));     \
    asm("tanh.approx.f16x2 %0, %1;" : "=r"(_t) : "r"(_x));             \
    asm("fma.rn.f16x2 %0, %1, %2, %3;"                                 \
        : "=r"(ch) : "r"(_t), "r"(vP), "r"(ch));                       \
} while (0)

#define FLUSH_H2(ch, acc) do {                                         \
    float _l, _h;                                                      \
    asm("{.reg .b16 l, h; mov.b32 {l, h}, %2;"                         \
        " cvt.f32.f16 %0, l; cvt.f32.f16 %1, h;}"                      \
        : "=f"(_l), "=f"(_h) : "r"(ch));                               \
    acc += _l; acc += _h;                                              \
} while (0)

// ---------------------------------------------------------------------------
// SGEMM core v4: 64x64 block tile, BK=32, 256 threads, 4x4 micro-tile.
// A staged TRANSPOSED [k][m] -> mainloop is 2x LDS.128 + 16 FFMA per kk
// (A-read is a 2-address broadcast within each warp). Double-buffered smem
// + register prefetch. Pitch 68 keeps LDS.128 16B-aligned & low-conflict.
// ---------------------------------------------------------------------------
__device__ __forceinline__ void gemm_core(
    const float* __restrict__ A, const float* __restrict__ W,
    float* __restrict__ C,
    int row0, int col0, int N, int K, int lda,
    float (&As)[2][32][68], float (&Ws)[2][32][68])
{
    const int tid = threadIdx.x;
    const int txn = tid & 15;    // 16 col groups * 4 = 64 cols
    const int tym = tid >> 4;    // 16 row groups * 4 = 64 rows

    float4 aF[2], wF[2];
    float acc[4][4] = {};

    auto loadChunk = [&](int k0) {
        #pragma unroll
        for (int i = 0; i < 2; i++) {
            int idx = tid + i * 256;
            int r  = idx >> 3;           // 0..63 (m)
            int kc = (idx & 7) * 4;      // 0..28 (k)
            aF[i] = *(const float4*)(A + (long)(row0 + r) * lda + k0 + kc);
        }
        #pragma unroll
        for (int i = 0; i < 2; i++) {
            int idx = tid + i * 256;
            int r = idx >> 4;            // 0..31 (k)
            int c = (idx & 15) * 4;      // n
            wF[i] = *(const float4*)(W + (long)(k0 + r) * N + col0 + c);
        }
    };
    auto storeChunk = [&](int buf) {
        #pragma unroll
        for (int i = 0; i < 2; i++) {
            int idx = tid + i * 256;
            int r  = idx >> 3;
            int kc = (idx & 7) * 4;
            As[buf][kc + 0][r] = aF[i].x;
            As[buf][kc + 1][r] = aF[i].y;
            As[buf][kc + 2][r] = aF[i].z;
            As[buf][kc + 3][r] = aF[i].w;
        }
        #pragma unroll
        for (int i = 0; i < 2; i++) {
            int idx = tid + i * 256;
            int r = idx >> 4;
            int c = (idx & 15) * 4;
            *(float4*)&Ws[buf][r][c] = wF[i];
        }
    };
    auto compute = [&](int buf) {
        #pragma unroll
        for (int kk = 0; kk < 32; kk++) {
            float4 a = *(const float4*)&As[buf][kk][tym * 4];
            float4 w = *(const float4*)&Ws[buf][kk][txn * 4];
            float ar[4] = {a.x, a.y, a.z, a.w};
            float wr[4] = {w.x, w.y, w.z, w.w};
            #pragma unroll
            for (int i = 0; i < 4; i++)
                #pragma unroll
                for (int j = 0; j < 4; j++)
                    acc[i][j] += ar[i] * wr[j];
        }
    };

    loadChunk(0);
    storeChunk(0);
    __syncthreads();

    int buf = 0;
    for (int k0 = 32; k0 < K; k0 += 32) {
        loadChunk(k0);
        compute(buf);
        storeChunk(buf ^ 1);
        __syncthreads();
        buf ^= 1;
    }
    compute(buf);

    #pragma unroll
    for (int i = 0; i < 4; i++) {
        int r = row0 + tym * 4 + i;
        float4 o;
        o.x = acc[i][0]; o.y = acc[i][1]; o.z = acc[i][2]; o.w = acc[i][3];
        *(float4*)(C + (long)r * N + col0 + txn * 4) = o;
    }
}

// ---------------------------------------------------------------------------
// Phase 1 mega-GEMM: pe = enc@W_h (yb 0..31), pq = q@W_s (32..39),
// qWo = q@W_out[H:2H] (40..47). All N=512, K=512. 384 blocks.
// ---------------------------------------------------------------------------
__global__ __launch_bounds__(256) void phase1_kernel(
    const float* __restrict__ enc, const float* __restrict__ query,
    const float* __restrict__ W_h, const float* __restrict__ W_s,
    const float* __restrict__ W_out)
{
    __shared__ float As[2][32][68];
    __shared__ float Ws[2][32][68];
    const int yb = blockIdx.y;
    const int col0 = blockIdx.x * 64;
    if (yb < 32) {
        gemm_core(enc, W_h, g_pe, yb * 64, col0, Hh, Hh, Hh, As, Ws);
    } else if (yb < 40) {
        gemm_core(query, W_s, g_pq, (yb - 32) * 64, col0, Hh, Hh, Hh, As, Ws);
    } else {
        gemm_core(query, W_out + (long)Hh * Hh, g_qWo,
                  (yb - 40) * 64, col0, Hh, Hh, Hh, As, Ws);
    }
}

// ---------------------------------------------------------------------------
// ctx split-K: partial[seg] = align[b][:, seg*128:...] @ enc[b][seg*128:...]
// grid (8, 2, 16): x = n-tile, y = m-tile, z = b*4+seg. 256 blocks.
// ---------------------------------------------------------------------------
__global__ __launch_bounds__(256) void ctx_kernel(const float* __restrict__ enc)
{
    __shared__ float As[2][32][68];
    __shared__ float Ws[2][32][68];
    const int b   = blockIdx.z & 3;
    const int seg = blockIdx.z >> 2;
    gemm_core(g_score + (long)b * Tt * Ss + seg * 128,
              enc + (long)b * Ss * Hh + (long)seg * 128 * Hh,
              g_cp + (long)seg * BTH + (long)b * Tt * Hh,
              blockIdx.y * 64, blockIdx.x * 64, Hh, 128, Ss, As, Ws);
}

__global__ __launch_bounds__(256) void ctx_reduce_kernel()
{
    int i = blockIdx.x * 256 + threadIdx.x;   // float4 index
    float4 a = ((const float4*)g_cp)[i];
    float4 b = ((const float4*)(g_cp + BTH))[i];
    float4 c = ((const float4*)(g_cp + 2 * BTH))[i];
    float4 d = ((const float4*)(g_cp + 3 * BTH))[i];
    float4 o;
    o.x = (a.x + b.x) + (c.x + d.x);
    o.y = (a.y + b.y) + (c.y + d.y);
    o.z = (a.z + b.z) + (c.z + d.z);
    o.w = (a.w + b.w) + (c.w + d.w);
    ((float4*)g_ctx)[i] = o;
}

// ---------------------------------------------------------------------------
// out split-K: partial[seg] = ctx[:, seg*128:...] @ W_out[seg*128:..., :]
// grid (8, 8, 4): z = seg. 256 blocks. Reduce adds qWo + tanh.
// ---------------------------------------------------------------------------
__global__ __launch_bounds__(256) void out_kernel(const float* __restrict__ W_out)
{
    __shared__ float As[2][32][68];
    __shared__ float Ws[2][32][68];
    const int seg = blockIdx.z;
    gemm_core(g_ctx + seg * 128,
              W_out + (long)seg * 128 * Hh,
              g_op + (long)seg * BTH,
              blockIdx.y * 64, blockIdx.x * 64, Hh, 128, Hh, As, Ws);
}

__global__ __launch_bounds__(256) void out_reduce_kernel(float* __restrict__ out)
{
    int i = blockIdx.x * 256 + threadIdx.x;   // float4 index
    float4 a = ((const float4*)g_op)[i];
    float4 b = ((const float4*)(g_op + BTH))[i];
    float4 c = ((const float4*)(g_op + 2 * BTH))[i];
    float4 d = ((const float4*)(g_op + 3 * BTH))[i];
    float4 q = ((const float4*)g_qWo)[i];
    float4 o;
    o.x = tanhf((a.x + b.x) + (c.x + d.x) + q.x);
    o.y = tanhf((a.y + b.y) + (c.y + d.y) + q.y);
    o.z = tanhf((a.z + b.z) + (c.z + d.z) + q.z);
    o.w = tanhf((a.w + b.w) + (c.w + d.w) + q.w);
    ((float4*)out)[i] = o;
}

// ---------------------------------------------------------------------------
// Score kernel (packed f16x2 tanh):
// score[b,t,s] = sum_h v[h] * tanh(pq[b,t,h] + pe[b,s,h])
// ---------------------------------------------------------------------------
__global__ __launch_bounds__(256) void score2_kernel(const float* __restrict__ v)
{
    __shared__ unsigned pe_p[64][68];   // [s][h-pair]
    __shared__ unsigned pq_p[16][68];   // [t][h-pair]
    __shared__ unsigned v_p[64];

    const int b  = blockIdx.z;
    const int t0 = blockIdx.y * 16;
    const int s0 = blockIdx.x * 64;
    const int tid = threadIdx.x;
    const int tx = tid & 31;   // s lane
    const int ty = tid >> 5;   // t pair (0..7)

    float acc00 = 0.f, acc01 = 0.f, acc10 = 0.f, acc11 = 0.f;

    for (int h0 = 0; h0 < Hh; h0 += 128) {
        for (int i = tid; i < 64 * 32; i += 256) {
            int r = i >> 5, q = i & 31;
            float4 x = *(const float4*)(g_pe + (long)(b * Ss + s0 + r) * Hh + h0 + q * 4);
            *(uint2*)&pe_p[r][q * 2] = make_uint2(pack_h2(x.x, x.y), pack_h2(x.z, x.w));
        }
        for (int i = tid; i < 16 * 32; i += 256) {
            int r = i >> 5, q = i & 31;
            float4 x = *(const float4*)(g_pq + (long)(b * Tt + t0 + r) * Hh + h0 + q * 4);
            *(uint2*)&pq_p[r][q * 2] = make_uint2(pack_h2(x.x, x.y), pack_h2(x.z, x.w));
        }
        if (tid < 32) {
            float4 x = *(const float4*)(v + h0 + tid * 4);
            *(uint2*)&v_p[tid * 2] = make_uint2(pack_h2(x.x, x.y), pack_h2(x.z, x.w));
        }
        __syncthreads();

        #pragma unroll 4
        for (int hp = 0; hp < 64; hp += 4) {   // 4 pairs = 8 h per chunk
            uint4 a0 = *(const uint4*)&pq_p[ty * 2 + 0][hp];
            uint4 a1 = *(const uint4*)&pq_p[ty * 2 + 1][hp];
            uint4 e0 = *(const uint4*)&pe_p[tx][hp];
            uint4 e1 = *(const uint4*)&pe_p[tx + 32][hp];
            uint4 vv = *(const uint4*)&v_p[hp];

            unsigned ch00 = 0u, ch01 = 0u, ch10 = 0u, ch11 = 0u;
            STEP_H2(a0.x, e0.x, vv.x, ch00); STEP_H2(a0.y, e0.y, vv.y, ch00);
            STEP_H2(a0.z, e0.z, vv.z, ch00); STEP_H2(a0.w, e0.w, vv.w, ch00);
            STEP_H2(a0.x, e1.x, vv.x, ch01); STEP_H2(a0.y, e1.y, vv.y, ch01);
            STEP_H2(a0.z, e1.z, vv.z, ch01); STEP_H2(a0.w, e1.w, vv.w, ch01);
            STEP_H2(a1.x, e0.x, vv.x, ch10); STEP_H2(a1.y, e0.y, vv.y, ch10);
            STEP_H2(a1.z, e0.z, vv.z, ch10); STEP_H2(a1.w, e0.w, vv.w, ch10);
            STEP_H2(a1.x, e1.x, vv.x, ch11); STEP_H2(a1.y, e1.y, vv.y, ch11);
            STEP_H2(a1.z, e1.z, vv.z, ch11); STEP_H2(a1.w, e1.w, vv.w, ch11);
            FLUSH_H2(ch00, acc00); FLUSH_H2(ch01, acc01);
            FLUSH_H2(ch10, acc10); FLUSH_H2(ch11, acc11);
        }
        __syncthreads();
    }

    const int t_a = t0 + ty * 2, t_b = t_a + 1;
    g_score[(long)(b * Tt + t_a) * Ss + s0 + tx]      = acc00;
    g_score[(long)(b * Tt + t_a) * Ss + s0 + tx + 32] = acc01;
    g_score[(long)(b * Tt + t_b) * Ss + s0 + tx]      = acc10;
    g_score[(long)(b * Tt + t_b) * Ss + s0 + tx + 32] = acc11;
}

// ---------------------------------------------------------------------------
// Masked softmax over S, in place on g_score.
// ---------------------------------------------------------------------------
__global__ __launch_bounds__(128) void softmax_kernel(const int* __restrict__ src_len)
{
    const int row = blockIdx.x;
    const int b = row / Tt;
    const int len = src_len[b];
    const int tid = threadIdx.x;
    float* sp = g_score + (long)row * Ss;

    __shared__ float redm[4];
    __shared__ float reds[4];

    const int sbase = tid * 4;
    float4 x4 = *(const float4*)(sp + sbase);
    float xv[4] = {x4.x, x4.y, x4.z, x4.w};
    #pragma unroll
    for (int i = 0; i < 4; i++)
        if (sbase + i >= len) xv[i] = -3.0e38f;

    float m = fmaxf(fmaxf(xv[0], xv[1]), fmaxf(xv[2], xv[3]));
    #pragma unroll
    for (int off = 16; off; off >>= 1)
        m = fmaxf(m, __shfl_xor_sync(0xffffffffu, m, off));
    if ((tid & 31) == 0) redm[tid >> 5] = m;
    __syncthreads();
    m = fmaxf(fmaxf(redm[0], redm[1]), fmaxf(redm[2], redm[3]));

    float e[4];
    float ssum = 0.f;
    #pragma unroll
    for (int i = 0; i < 4; i++) {
        e[i] = (sbase + i < len) ? expf(xv[i] - m) : 0.f;
        ssum += e[i];
    }
    #pragma unroll
    for (int off = 16; off; off >>= 1)
        ssum += __shfl_xor_sync(0xffffffffu, ssum, off);
    if ((tid & 31) == 0) reds[tid >> 5] = ssum;
    __syncthreads();
    ssum = reds[0] + reds[1] + reds[2] + reds[3];

    const float inv = 1.0f / ssum;
    float4 o;
    o.x = e[0] * inv; o.y = e[1] * inv; o.z = e[2] * inv; o.w = e[3] * inv;
    *(float4*)(sp + sbase) = o;
}

// ---------------------------------------------------------------------------
// Launch
// ---------------------------------------------------------------------------
extern "C" void kernel_launch(void* const* d_in, const int* in_sizes, int n_in,
                              void* d_out, int out_size)
{
    const float* query = (const float*)d_in[0];  // (B,T,H)
    const float* enc   = (const float*)d_in[1];  // (B,S,H)
    const int*   slen  = (const int*)d_in[2];    // (B,)
    const float* W_h   = (const float*)d_in[3];  // (H,H)
    const float* W_s   = (const float*)d_in[4];  // (H,H)
    const float* v     = (const float*)d_in[5];  // (H,)
    const float* W_out = (const float*)d_in[6];  // (2H,H)
    float* out = (float*)d_out;                  // (B,T,H)

    // 1) pe, pq, qWo in one launch (384 blocks, 256 thr)
    phase1_kernel<<<dim3(8, 48, 1), 256>>>(enc, query, W_h, W_s, W_out);

    // 2) scores (f16x2 tanh)
    score2_kernel<<<dim3(Ss / 64, Tt / 16, Bb), 256>>>(v);

    // 3) masked softmax (in place -> alignment)
    softmax_kernel<<<Bb * Tt, 128>>>(slen);

    // 4) context = alignment @ encoder : split-K 4 (256 blocks) + reduce
    ctx_kernel<<<dim3(8, 2, 16), 256>>>(enc);
    ctx_reduce_kernel<<<BTH / 4 / 256, 256>>>();

    // 5) out = tanh(ctx @ W_out[0:H] + qWo) : split-K 4 (256 blocks) + reduce
    out_kernel<<<dim3(8, 8, 4), 256>>>(W_out);
    out_reduce_kernel<<<BTH / 4 / 256, 256>>>(out);
}